// round 15
// baseline (speedup 1.0000x reference)
#include <cuda_runtime.h>
#include <cstddef>
#include <cstdint>

#define B_   2
#define N_   768
#define BN_  1536
#define D_   512
#define E_   64
#define LN_EPS 1e-5f
#define PADR 68            // epilogue smem row pitch (floats)
#define JT   8             // j-tiles per block in epilogue
#define NBLK 576           // total blocks (single wave at 4/SM: 592 capacity)

typedef unsigned long long ull;

// ---------------- scratch ----------------
__device__ float g_WR[D_ * E_];          // fused W_edges@W_rows, [d][f]
__device__ float g_WC[D_ * E_];          // fused W_edges@W_cols, [d][f]
__device__ float g_pR[4 * BN_ * E_];     // partial row-GEMM, [part][row][f]
__device__ float g_pC[4 * BN_ * E_];
__device__ float g_Rc[BN_ * E_];         // centered R'
__device__ float g_Cc[BN_ * E_];         // centered C'
__device__ float g_varR[BN_];
__device__ float g_varC[BN_];
__device__ int   g_bar0 = 0, g_bar1 = 0, g_bar2 = 0, g_done = 0;

// grid-wide barrier: all NBLK blocks co-resident by construction
__device__ __forceinline__ void gridbar(int* ctr) {
    __syncthreads();
    if (threadIdx.x == 0) {
        __threadfence();
        atomicAdd(ctr, 1);
        while (atomicAdd(ctr, 0) < NBLK) { __nanosleep(64); }
        __threadfence();
    }
    __syncthreads();
}

extern __shared__ float sm[];

__global__ void __launch_bounds__(256, 4) kAll(
        const float* __restrict__ x,
        const float* __restrict__ Wr,
        const float* __restrict__ Wc,
        const float* __restrict__ We,
        const float* __restrict__ gamma,
        const float* __restrict__ beta,
        float* __restrict__ out) {
    int tid = threadIdx.x;
    int bid = blockIdx.x;

    // ================= Phase 0: weight fusion (blocks 0..63) =================
    {
        int gid = bid * 256 + tid;
        if (gid < 16384) {
            int d  = gid & 511;          // coalesced across warp
            int fh = gid >> 9;           // warp-uniform (broadcast We reads)
            const float* we0 = We + fh * E_;
            const float* we1 = We + (fh + 32) * E_;
            float ar0 = 0.f, ar1 = 0.f, ac0 = 0.f, ac1 = 0.f;
#pragma unroll 8
            for (int e = 0; e < E_; e++) {
                float wr = Wr[(size_t)e * D_ + d];
                float wc = Wc[(size_t)e * D_ + d];
                float w0 = we0[e], w1 = we1[e];
                ar0 = fmaf(w0, wr, ar0); ar1 = fmaf(w1, wr, ar1);
                ac0 = fmaf(w0, wc, ac0); ac1 = fmaf(w1, wc, ac1);
            }
            g_WR[d * E_ + fh]      = ar0;
            g_WR[d * E_ + fh + 32] = ar1;
            g_WC[d * E_ + fh]      = ac0;
            g_WC[d * E_ + fh + 32] = ac1;
        }
    }
    gridbar(&g_bar0);

    // ============ Phase 1: partial row GEMM (blocks 0..511) ==================
    // block = (tile t: 12 rows, part p: 128 dd). Weights L2-hot from phase 0.
    if (bid < 512) {
        int p = bid >> 7;                // 0..3
        int t = bid & 127;               // 0..127
        int row0 = t * 12;
        int d0   = p * 128;
        float* xs = sm;                  // 12 x 130 = 1560 floats
        for (int idx = tid; idx < 12 * 128; idx += 256) {
            int r = idx >> 7, dd = idx & 127;
            xs[r * 130 + dd] = x[(size_t)(row0 + r) * D_ + d0 + dd];
        }
        __syncthreads();

        int f  = tid & 63;
        int rg = tid >> 6;               // rows rg*3 .. rg*3+2
        float aR[3] = {0.f, 0.f, 0.f};
        float aC[3] = {0.f, 0.f, 0.f};
        const float* xrow = xs + rg * 3 * 130;
#pragma unroll 4
        for (int dd = 0; dd < 128; dd++) {
            float wr = g_WR[(d0 + dd) * E_ + f];
            float wc = g_WC[(d0 + dd) * E_ + f];
#pragma unroll
            for (int r = 0; r < 3; r++) {
                float xv = xrow[r * 130 + dd];
                aR[r] = fmaf(xv, wr, aR[r]);
                aC[r] = fmaf(xv, wc, aC[r]);
            }
        }
#pragma unroll
        for (int r = 0; r < 3; r++) {
            int row = row0 + rg * 3 + r;
            g_pR[((size_t)p * BN_ + row) * E_ + f] = aR[r];
            g_pC[((size_t)p * BN_ + row) * E_ + f] = aC[r];
        }
    }
    gridbar(&g_bar1);

    // ============ Phase 2: reduce partials + stats + centering (blocks 0..383)
    if (bid < 384) {
        float* red = sm;                 // 8 warps x 4 quantities
        int f  = tid & 63;
        int rg = tid >> 6;
        int row = bid * 4 + rg;
        float aR = 0.f, aC = 0.f;
#pragma unroll
        for (int p = 0; p < 4; p++) {
            aR += g_pR[((size_t)p * BN_ + row) * E_ + f];
            aC += g_pC[((size_t)p * BN_ + row) * E_ + f];
        }
        float sR = aR, qR = aR * aR, sC = aC, qC = aC * aC;
#pragma unroll
        for (int o = 16; o; o >>= 1) {
            sR += __shfl_xor_sync(0xffffffffu, sR, o);
            qR += __shfl_xor_sync(0xffffffffu, qR, o);
            sC += __shfl_xor_sync(0xffffffffu, sC, o);
            qC += __shfl_xor_sync(0xffffffffu, qC, o);
        }
        int w = tid >> 5;
        if ((tid & 31) == 0) {
            red[w * 4 + 0] = sR; red[w * 4 + 1] = qR;
            red[w * 4 + 2] = sC; red[w * 4 + 3] = qC;
        }
        __syncthreads();
        int wp = w ^ 1;
        float tR = red[w * 4 + 0] + red[wp * 4 + 0];
        float tQ = red[w * 4 + 1] + red[wp * 4 + 1];
        float tC = red[w * 4 + 2] + red[wp * 4 + 2];
        float tP = red[w * 4 + 3] + red[wp * 4 + 3];
        float mR = tR * (1.f / 64.f);
        float mC = tC * (1.f / 64.f);
        g_Rc[row * E_ + f] = aR - mR;
        g_Cc[row * E_ + f] = aC - mC;
        if (f == 0) {
            g_varR[row] = tQ * (1.f / 64.f) - mR * mR;
            g_varC[row] = tP * (1.f / 64.f) - mC * mC;
        }
    }
    gridbar(&g_bar2);

    // ============ Phase 3: epilogue (R12 kC body, bid remapped) ==============
    {
        float* rs  = sm;                 // 1088
        float* cs0 = sm + 1088;          // 1088
        float* cs1 = sm + 2176;          // 1088
        float* vR  = sm + 3264;          // 16
        float* vC0 = sm + 3280;          // 16
        float* vC1 = sm + 3296;          // 16
        float* inv = sm + 3312;          // 256

        int i0 = (bid % 48) * 16;
        int b  = (bid / 48) & 1;
        int jg = bid / 96;               // 0..5
        int rowR = b * N_ + i0;
        int rw = tid >> 4;
        int f4 = tid & 15;

        ((float4*)(rs + rw * PADR))[f4] =
            ((const float4*)(g_Rc + (size_t)(rowR + rw) * E_))[f4];
        if (tid < 16) vR[tid] = g_varR[rowR + tid];
        {
            int rowC = b * N_ + jg * JT * 16;
            ((float4*)(cs0 + rw * PADR))[f4] =
                ((const float4*)(g_Cc + (size_t)(rowC + rw) * E_))[f4];
            if (tid < 16) vC0[tid] = g_varC[rowC + tid];
        }
        __syncthreads();

        float4 gm = __ldg((const float4*)gamma + f4);
        float4 bt = __ldg((const float4*)beta + f4);
        float4 rr = ((const float4*)(rs + rw * PADR))[f4];
        float4 u;
        u.x = rr.x * gm.x; u.y = rr.y * gm.y; u.z = rr.z * gm.z; u.w = rr.w * gm.w;

        for (int t = 0; t < JT; t++) {
            float* csc = (t & 1) ? cs1 : cs0;
            float* csn = (t & 1) ? cs0 : cs1;
            float* vCc = (t & 1) ? vC1 : vC0;
            float* vCn = (t & 1) ? vC0 : vC1;

            float4 pc;
            float pv = 0.f;
            if (t + 1 < JT) {
                int rowCn = b * N_ + (jg * JT + t + 1) * 16;
                pc = ((const float4*)(g_Cc + (size_t)(rowCn + rw) * E_))[f4];
                if (tid < 16) pv = g_varC[rowCn + tid];
            }

            {
                int ii = tid >> 4, jj = tid & 15;
                const float4* r4 = (const float4*)(rs + ii * PADR);
                const float4* c4 = (const float4*)(csc + jj * PADR);
                float d = 0.f;
#pragma unroll
                for (int k = 0; k < 16; k++) {
                    float4 a = r4[k], c = c4[k];
                    d = fmaf(a.x, c.x, d);
                    d = fmaf(a.y, c.y, d);
                    d = fmaf(a.z, c.z, d);
                    d = fmaf(a.w, c.w, d);
                }
                float var = vR[ii] + vCc[jj] + d * (2.f / 64.f);
                inv[tid] = rsqrtf(var + LN_EPS);
            }
            __syncthreads();

            const float4* ivp = (const float4*)(inv + rw * 16);
            float4 iva = ivp[0], ivb = ivp[1], ivc = ivp[2], ivd = ivp[3];
            float ivs[16] = {iva.x, iva.y, iva.z, iva.w, ivb.x, ivb.y, ivb.z, ivb.w,
                             ivc.x, ivc.y, ivc.z, ivc.w, ivd.x, ivd.y, ivd.z, ivd.w};
            float4* op = (float4*)out +
                         ((size_t)(b * N_ + i0 + rw) * N_ + (jg * JT + t) * 16) * 16 + f4;
#pragma unroll
            for (int jj = 0; jj < 16; jj++) {
                float4 c = ((const float4*)(csc + jj * PADR))[f4];
                float iv = ivs[jj];
                float4 o;
                o.x = fmaf(fmaf(c.x, gm.x, u.x), iv, bt.x);
                o.y = fmaf(fmaf(c.y, gm.y, u.y), iv, bt.y);
                o.z = fmaf(fmaf(c.z, gm.z, u.z), iv, bt.z);
                o.w = fmaf(fmaf(c.w, gm.w, u.w), iv, bt.w);
                __stcs(op + (size_t)jj * 16, o);
            }

            if (t + 1 < JT) {
                ((float4*)(csn + rw * PADR))[f4] = pc;
                if (tid < 16) vCn[tid] = pv;
            }
            __syncthreads();
        }
    }

    // ---- reset barrier counters for the next graph replay ----
    if (tid == 0) {
        int d = atomicAdd(&g_done, 1);
        if (d == NBLK - 1) {
            g_bar0 = 0; g_bar1 = 0; g_bar2 = 0; g_done = 0;
            __threadfence();
        }
    }
}

// ---------------- launch -------------------------------------------------------
#define KALL_SMEM (3568 * 4)

extern "C" void kernel_launch(void* const* d_in, const int* in_sizes, int n_in,
                              void* d_out, int out_size) {
    const float* x     = (const float*)d_in[0];  // [2,768,512]
    const float* Wr    = (const float*)d_in[1];  // [64,512]
    const float* Wc    = (const float*)d_in[2];  // [64,512]
    const float* We    = (const float*)d_in[3];  // [64,64]
    const float* gamma = (const float*)d_in[4];  // [64]
    const float* beta  = (const float*)d_in[5];  // [64]
    float* out = (float*)d_out;                  // [2,768,768,64] fp32

    kAll<<<NBLK, 256, KALL_SMEM>>>(x, Wr, Wc, We, gamma, beta, out);
}